// round 6
// baseline (speedup 1.0000x reference)
#include <cuda_runtime.h>
#include <cuda_bf16.h>
#include <math_constants.h>
#include <cstdint>

// Problem constants
#define DD     1024
#define NB     64
#define SS     36
#define LL     32
#define SMOOTHF 9.0f
#define LAMBDAF 6.0f
#define EPSF   1e-8f

#define MROWS  (NB*SS)       // 2304 image rows
#define CROWS  (NB*LL)       // 2048 caption rows
#define AROWS  (2*MROWS)     // 4608 = [images ; Y]
#define KSPLIT 3072          // K after [hi|lo|hi] concat
#define XCOLS  CROWS         // 2048

#define BK 64                        // bf16 elems per chunk = 128 B rows
#define NCHUNK (KSPLIT / BK)         // 48
#define NSTAGE 3

// Scratch (static device globals; allocation forbidden)
__device__ __nv_bfloat16 g_A2[(size_t)AROWS * KSPLIT];  // [images-split ; Y-split]
__device__ __nv_bfloat16 g_B2[(size_t)CROWS * KSPLIT];  // captions split
__device__ __nv_bfloat16 g_BW[(size_t)DD   * KSPLIT];   // W_g^T split
__device__ float g_X[(size_t)AROWS * XCOLS];            // fused GEMM output fp32
__device__ float g_G[NB * SS * SS];
__device__ float g_w1[CROWS];

// ---------------------------------------------------------------------------
// PTX helpers (base-ISA only: cp.async, ldmatrix, mma.sync)
// ---------------------------------------------------------------------------
__device__ __forceinline__ uint32_t smem_u32(const void* p) {
    uint32_t a;
    asm("{ .reg .u64 t; cvta.to.shared.u64 t, %1; cvt.u32.u64 %0, t; }" : "=r"(a) : "l"(p));
    return a;
}
#define CP_ASYNC16(dst, src) \
    asm volatile("cp.async.cg.shared.global [%0], [%1], 16;\n" :: "r"(dst), "l"(src))
#define CP_COMMIT() asm volatile("cp.async.commit_group;\n" ::: "memory")
#define CP_WAIT(n)  asm volatile("cp.async.wait_group %0;\n" :: "n"(n) : "memory")

__device__ __forceinline__ void ldsm4(uint32_t* r, uint32_t addr) {
    asm volatile("ldmatrix.sync.aligned.m8n8.x4.shared.b16 {%0,%1,%2,%3}, [%4];"
                 : "=r"(r[0]), "=r"(r[1]), "=r"(r[2]), "=r"(r[3]) : "r"(addr));
}
__device__ __forceinline__ void mma16816(float* c, const uint32_t* a,
                                         uint32_t b0, uint32_t b1) {
    asm volatile("mma.sync.aligned.m16n8k16.row.col.f32.bf16.bf16.f32 "
                 "{%0,%1,%2,%3}, {%4,%5,%6,%7}, {%8,%9}, {%0,%1,%2,%3};"
                 : "+f"(c[0]), "+f"(c[1]), "+f"(c[2]), "+f"(c[3])
                 : "r"(a[0]), "r"(a[1]), "r"(a[2]), "r"(a[3]), "r"(b0), "r"(b1));
}
// SW128 swizzle for 128B rows
__device__ __forceinline__ uint32_t swz(int row, int seg) {
    return (uint32_t)(row * 128 + (seg ^ ((row & 7) << 4)));
}

// ---------------------------------------------------------------------------
// Split kernels
// A-side pattern: [hi | lo | hi]; B-side pattern: [hi | hi | lo]
// ---------------------------------------------------------------------------
__global__ void split_rows_kernel(const float* __restrict__ src, __nv_bfloat16* __restrict__ dst,
                                  int loOff, int dupOff)
{
    int idx = blockIdx.x * 256 + threadIdx.x;
    int row = idx >> 10, col = idx & 1023;
    float f = src[idx];
    __nv_bfloat16 hi = __float2bfloat16(f);
    __nv_bfloat16 lo = __float2bfloat16(f - __bfloat162float(hi));
    size_t r = (size_t)row * KSPLIT;
    dst[r + col] = hi;
    dst[r + loOff + col] = lo;
    dst[r + dupOff + col] = hi;
}

__global__ void split_w_kernel(const float* __restrict__ W)
{
    __shared__ float t[32][33];
    int k0 = blockIdx.y * 32, n0 = blockIdx.x * 32;
    int tx = threadIdx.x, ty = threadIdx.y;
    t[ty][tx] = W[(size_t)(k0 + ty) * DD + n0 + tx];
    __syncthreads();
    float f = t[tx][ty];                       // = W[k0+tx][n0+ty]
    __nv_bfloat16 hi = __float2bfloat16(f);
    __nv_bfloat16 lo = __float2bfloat16(f - __bfloat162float(hi));
    size_t r = (size_t)(n0 + ty) * KSPLIT;
    g_BW[r + k0 + tx] = hi;
    g_BW[r + 1024 + k0 + tx] = hi;
    g_BW[r + 2048 + k0 + tx] = lo;
}

// ---------------------------------------------------------------------------
// HMMA NT GEMM: C[m,n] = sum_k A[m,k]*B[n,k], K = KSPLIT.
// Templated tile / warp layout; 3-stage cp.async, single barrier per chunk,
// register double-buffered ldmatrix fragments.
// mode 0: write fp32 C (ldc). mode 1: write split bf16 rows [hi|lo|hi] into Aout.
// ---------------------------------------------------------------------------
template<int BM, int BN, int WARPS_M, int WARPS_N, int MIN_CTAS>
__global__ __launch_bounds__(WARPS_M * WARPS_N * 32, MIN_CTAS)
void gemm_mma_kernel(const __nv_bfloat16* __restrict__ A,
                     const __nv_bfloat16* __restrict__ B,
                     float* __restrict__ C,
                     __nv_bfloat16* __restrict__ Aout,
                     int mode, int ldc)
{
    constexpr int THREADS = WARPS_M * WARPS_N * 32;
    constexpr int MT  = BM / WARPS_M / 16;   // A 16-row subtiles per warp
    constexpr int NT2 = BN / WARPS_N / 16;   // B 16-row ldsm tiles per warp
    constexpr int NJ  = NT2 * 2;             // n8 column groups per warp
    constexpr int A_BYTES = BM * 128;
    constexpr int B_BYTES = BN * 128;
    constexpr int STAGE_BYTES = A_BYTES + B_BYTES;
    constexpr int A_IT = BM * 8 / THREADS;
    constexpr int B_IT = BN * 8 / THREADS;

    extern __shared__ char smem_raw[];
    const uint32_t sbase = (smem_u32(smem_raw) + 1023u) & ~1023u;

    const int tid = threadIdx.x;
    const int wid = tid >> 5, lane = tid & 31;
    const int wm = wid / WARPS_N;
    const int wn = wid % WARPS_N;
    const size_t arow0 = (size_t)blockIdx.y * BM;
    const size_t brow0 = (size_t)blockIdx.x * BN;

    const int lr = lane & 15;
    const int lseg = (lane >> 4) * 16;

    float acc[MT][NJ][4];
#pragma unroll
    for (int mt = 0; mt < MT; mt++)
#pragma unroll
        for (int j = 0; j < NJ; j++)
#pragma unroll
            for (int e = 0; e < 4; e++) acc[mt][j][e] = 0.f;

    uint32_t af[2][MT][4], bf[2][NT2][4];

    const char* Abase = (const char*)(A + arow0 * KSPLIT);
    const char* Bbase = (const char*)(B + brow0 * KSPLIT);
    auto load_chunk = [&](int c, int s) {
        const uint32_t sA = sbase + s * STAGE_BYTES;
        const uint32_t sB = sA + A_BYTES;
        const size_t cb = (size_t)c * 128;
#pragma unroll
        for (int i = 0; i < A_IT; i++) {
            int p = tid + i * THREADS;
            int r = p >> 3, seg = (p & 7) * 16;
            CP_ASYNC16(sA + swz(r, seg), Abase + (size_t)r * (KSPLIT * 2) + cb + seg);
        }
#pragma unroll
        for (int i = 0; i < B_IT; i++) {
            int p = tid + i * THREADS;
            int r = p >> 3, seg = (p & 7) * 16;
            CP_ASYNC16(sB + swz(r, seg), Bbase + (size_t)r * (KSPLIT * 2) + cb + seg);
        }
        CP_COMMIT();
    };

    auto ldfrag = [&](int s, int kk, int buf) {
        const uint32_t sA = sbase + s * STAGE_BYTES;
        const uint32_t sB = sA + A_BYTES;
#pragma unroll
        for (int mt = 0; mt < MT; mt++)
            ldsm4(af[buf][mt], sA + swz(wm * (MT * 16) + mt * 16 + lr, kk * 32 + lseg));
#pragma unroll
        for (int nt = 0; nt < NT2; nt++)
            ldsm4(bf[buf][nt], sB + swz(wn * (NT2 * 16) + nt * 16 + lr, kk * 32 + lseg));
    };

    auto domma = [&](int buf) {
#pragma unroll
        for (int mt = 0; mt < MT; mt++)
#pragma unroll
            for (int nt = 0; nt < NT2; nt++)
#pragma unroll
                for (int h = 0; h < 2; h++)
                    mma16816(acc[mt][nt * 2 + h], af[buf][mt],
                             bf[buf][nt][h], bf[buf][nt][h + 2]);
    };

    load_chunk(0, 0);
    load_chunk(1, 1);

    for (int c = 0; c < NCHUNK; c++) {
        // Ensure chunk c complete (committed >=2 iterations ago).
        if (c + 1 < NCHUNK) { CP_WAIT(1); } else { CP_WAIT(0); }
        __syncthreads();   // cross-thread visibility of chunk c + all warps done with stage (c+2)%3's old tenant
        if (c + 2 < NCHUNK) load_chunk(c + 2, (c + 2) % NSTAGE);
        const int s = c % NSTAGE;
        ldfrag(s, 0, 0);
#pragma unroll
        for (int kk = 0; kk < 4; kk++) {
            if (kk < 3) ldfrag(s, kk + 1, (kk + 1) & 1);
            domma(kk & 1);
        }
    }

    // Epilogue. C-frag mapping: lane l -> rows (l>>2, l>>2+8), cols 2*(l&3)+{0,1}.
    const int r0 = lane >> 2;
    const int cb2 = 2 * (lane & 3);
    if (mode == 0) {
#pragma unroll
        for (int mt = 0; mt < MT; mt++) {
#pragma unroll
            for (int j = 0; j < NJ; j++) {
                size_t row = arow0 + wm * (MT * 16) + mt * 16 + r0;
                size_t col = brow0 + wn * (NJ * 8) + j * 8 + cb2;
                *(float2*)(C + row * ldc + col)       = make_float2(acc[mt][j][0], acc[mt][j][1]);
                *(float2*)(C + (row + 8) * ldc + col) = make_float2(acc[mt][j][2], acc[mt][j][3]);
            }
        }
    } else {
#pragma unroll
        for (int mt = 0; mt < MT; mt++) {
#pragma unroll
            for (int j = 0; j < NJ; j++) {
                int col = (int)brow0 + wn * (NJ * 8) + j * 8 + cb2;   // < 1024
#pragma unroll
                for (int h = 0; h < 2; h++) {
                    size_t row = arow0 + wm * (MT * 16) + mt * 16 + r0 + h * 8;
                    __nv_bfloat16* dr = Aout + row * KSPLIT;
                    float f0 = acc[mt][j][2 * h], f1 = acc[mt][j][2 * h + 1];
                    __nv_bfloat16 h0 = __float2bfloat16(f0);
                    __nv_bfloat16 h1 = __float2bfloat16(f1);
                    __nv_bfloat16 l0 = __float2bfloat16(f0 - __bfloat162float(h0));
                    __nv_bfloat16 l1 = __float2bfloat16(f1 - __bfloat162float(h1));
                    __nv_bfloat162 hv; hv.x = h0; hv.y = h1;
                    __nv_bfloat162 lv; lv.x = l0; lv.y = l1;
                    *(__nv_bfloat162*)(dr + col)        = hv;
                    *(__nv_bfloat162*)(dr + 1024 + col) = lv;
                    *(__nv_bfloat162*)(dr + 2048 + col) = hv;
                }
            }
        }
    }
}

// ---------------------------------------------------------------------------
// Per-image Gram matrix
// ---------------------------------------------------------------------------
__global__ void gram_kernel(const float* __restrict__ images)
{
    __shared__ float T[SS][65];
    const int b = blockIdx.x;
    const int tid = threadIdx.x;
    float acc[6] = {0.f, 0.f, 0.f, 0.f, 0.f, 0.f};
    for (int d0 = 0; d0 < DD; d0 += 64) {
        __syncthreads();
        for (int i = tid; i < SS * 64; i += 256) {
            int r = i / 64, c = i % 64;
            T[r][c] = images[((size_t)b * SS + r) * DD + d0 + c];
        }
        __syncthreads();
#pragma unroll
        for (int pi = 0; pi < 6; pi++) {
            int p = tid + pi * 256;
            if (p < SS * SS) {
                int s = p / SS, s2 = p % SS;
                float sum = 0.f;
#pragma unroll
                for (int k = 0; k < 64; k++) sum += T[s][k] * T[s2][k];
                acc[pi] += sum;
            }
        }
    }
#pragma unroll
    for (int pi = 0; pi < 6; pi++) {
        int p = tid + pi * 256;
        if (p < SS * SS) g_G[b * SS * SS + p] = acc[pi];
    }
}

__global__ void w1_kernel(const float* __restrict__ captions)
{
    const int row = blockIdx.x * 8 + (threadIdx.x >> 5);
    const int lane = threadIdx.x & 31;
    const float* p = captions + (size_t)row * DD;
    float s = 0.f;
    for (int k = lane; k < DD; k += 32) { float v = p[k]; s += v * v; }
#pragma unroll
    for (int o = 16; o; o >>= 1) s += __shfl_xor_sync(0xffffffffu, s, o);
    if (lane == 0) g_w1[row] = sqrtf(s);
}

// ---------------------------------------------------------------------------
// Final epilogue: one block per (caption i, image b)
// ---------------------------------------------------------------------------
__global__ __launch_bounds__(128)
void epilogue_kernel(const int* __restrict__ cap_lens, float* __restrict__ out)
{
    const int i = blockIdx.x;
    const int b = blockIdx.y;

    __shared__ float sA[SS][LL];
    __shared__ float sC[SS][LL];
    __shared__ float sQ[SS][LL];
    __shared__ float sG[SS][SS];
    __shared__ float snorm[SS];

    const int tid = threadIdx.x;
    const int len = cap_lens[i];

    for (int p = tid; p < SS * SS; p += 128)
        sG[p / SS][p % SS] = g_G[b * SS * SS + p];

    for (int p = tid; p < SS * LL; p += 128) {
        int s = p / LL, l = p % LL;
        size_t col = (size_t)i * LL + l;
        float a = g_X[(size_t)(MROWS + b * SS + s) * XCOLS + col];  // attn logits (Y.cap)
        a = (a > 0.f) ? a : 0.1f * a;
        if (l >= len) a = 0.f;
        sA[s][l] = a;
        sC[s][l] = g_X[(size_t)(b * SS + s) * XCOLS + col];          // cap . img
    }
    __syncthreads();

    if (tid < SS) {
        float s2 = 0.f;
#pragma unroll
        for (int l = 0; l < LL; l++) { float v = sA[tid][l]; s2 += v * v; }
        snorm[tid] = 1.f / (sqrtf(s2) + EPSF);
    }
    __syncthreads();

    if (tid < LL) {
        const int l = tid;
        float vals[SS];
        float m = -CUDART_INF_F;
#pragma unroll
        for (int s = 0; s < SS; s++) {
            float v = sA[s][l] * snorm[s] * SMOOTHF;
            vals[s] = v;
            m = fmaxf(m, v);
        }
        float sum = 0.f;
#pragma unroll
        for (int s = 0; s < SS; s++) {
            float e = expf(vals[s] - m);
            vals[s] = e;
            sum += e;
        }
        float inv = 1.f / sum;
#pragma unroll
        for (int s = 0; s < SS; s++) sA[s][l] = vals[s] * inv;
    }
    __syncthreads();

    for (int p = tid; p < SS * LL; p += 128) {
        int s = p / LL, l = p % LL;
        float sum = 0.f;
#pragma unroll
        for (int s2 = 0; s2 < SS; s2++) sum += sG[s][s2] * sA[s2][l];
        sQ[s][l] = sum;
    }
    __syncthreads();

    if (tid < LL) {
        const int l = tid;
        float w12 = 0.f, w2q = 0.f;
#pragma unroll
        for (int s = 0; s < SS; s++) {
            float p = sA[s][l];
            w12 += p * sC[s][l];
            w2q += p * sQ[s][l];
        }
        float w2 = sqrtf(fmaxf(w2q, 0.f));
        float w1 = g_w1[i * LL + l];
        float r = w12 / fmaxf(w1 * w2, EPSF);

        float z = (l < len) ? r * LAMBDAF : -CUDART_INF_F;
        float m = z;
#pragma unroll
        for (int o = 16; o; o >>= 1) m = fmaxf(m, __shfl_xor_sync(0xffffffffu, m, o));
        float e = (l < len) ? expf(z - m) : 0.f;
#pragma unroll
        for (int o = 16; o; o >>= 1) e += __shfl_xor_sync(0xffffffffu, e, o);
        if (l == 0) out[b * NB + i] = (logf(e) + m) / LAMBDAF;
    }
}

// ---------------------------------------------------------------------------
extern "C" void kernel_launch(void* const* d_in, const int* in_sizes, int n_in,
                              void* d_out, int out_size)
{
    const float* images   = (const float*)d_in[0];  // (64, 36, 1024)
    const float* captions = (const float*)d_in[1];  // (64, 32, 1024)
    const int*   cap_lens = (const int*)  d_in[2];  // (64,)
    const float* W_g      = (const float*)d_in[3];  // (1024, 1024)
    float* out = (float*)d_out;                     // (64, 64)

    __nv_bfloat16 *pA2, *pB2, *pBW;
    float *pX;
    cudaGetSymbolAddress((void**)&pA2, g_A2);
    cudaGetSymbolAddress((void**)&pB2, g_B2);
    cudaGetSymbolAddress((void**)&pBW, g_BW);
    cudaGetSymbolAddress((void**)&pX,  g_X);

    // P variant: BM=64, BN=64, warps 2x2, 4 CTAs/SM.  smem = 3*(64+64)*128 + 1024 = 50176
    // X variant: BM=128, BN=128, warps 2x4, 2 CTAs/SM. smem = 3*(128+128)*128 + 1024 = 99328
    const int SMEM_P = NSTAGE * (64 + 64) * 128 + 1024;
    const int SMEM_X = NSTAGE * (128 + 128) * 128 + 1024;
    cudaFuncSetAttribute((const void*)gemm_mma_kernel<64, 64, 2, 2, 4>,
                         cudaFuncAttributeMaxDynamicSharedMemorySize, SMEM_P);
    cudaFuncSetAttribute((const void*)gemm_mma_kernel<128, 128, 2, 4, 2>,
                         cudaFuncAttributeMaxDynamicSharedMemorySize, SMEM_X);

    // 1) Splits
    split_rows_kernel<<<MROWS * DD / 256, 256>>>(images, pA2, 1024, 2048);   // [hi|lo|hi]
    split_rows_kernel<<<CROWS * DD / 256, 256>>>(captions, pB2, 2048, 1024); // [hi|hi|lo]
    {
        dim3 grid(DD / 32, DD / 32);
        split_w_kernel<<<grid, dim3(32, 32)>>>(W_g);
    }

    // 2) GEMM-P: Y = images @ W_g -> split bf16 into g_A2 rows [2304, 4608)
    //    grid (16, 36) = 576 CTAs, 128 threads, 4 CTAs/SM
    {
        dim3 grid(DD / 64, MROWS / 64);
        gemm_mma_kernel<64, 64, 2, 2, 4><<<grid, 128, SMEM_P>>>(pA2, pBW, nullptr,
                                                                pA2 + (size_t)MROWS * KSPLIT, 1, 0);
    }
    // 3) GEMM-X: X = [images ; Y] @ captions^T  (4608 x 2048, fp32)
    //    grid (16, 36) = 576 CTAs, 256 threads, 2 CTAs/SM
    {
        dim3 grid(XCOLS / 128, AROWS / 128);
        gemm_mma_kernel<128, 128, 2, 4, 2><<<grid, 256, SMEM_X>>>(pA2, pB2, pX, nullptr, 0, XCOLS);
    }

    // 4) Gram + caption norms
    gram_kernel<<<NB, 256>>>(images);
    w1_kernel<<<CROWS / 8, 256>>>(captions);

    // 5) Final epilogue
    {
        dim3 grid(NB, NB);
        epilogue_kernel<<<grid, 128>>>(cap_lens, out);
    }
}

// round 7
// speedup vs baseline: 1.2100x; 1.2100x over previous
#include <cuda_runtime.h>
#include <cuda_fp16.h>
#include <math_constants.h>
#include <cstdint>

// Problem constants
#define DD     1024
#define NB     64
#define SS     36
#define LL     32
#define SMOOTHF 9.0f
#define LAMBDAF 6.0f
#define EPSF   1e-8f

#define MROWS  (NB*SS)       // 2304 image rows
#define CROWS  (NB*LL)       // 2048 caption rows
#define AROWS  (2*MROWS)     // 4608 = [images ; Y]
#define KSPLIT 2048          // K after fp16 [hi|lo] (A-side) / [hi|hi] (B-side) concat
#define XCOLS  CROWS         // 2048

#define BK 64                        // fp16 elems per chunk = 128 B rows
#define NCHUNK (KSPLIT / BK)         // 32
#define NSTAGE 3

// Scratch (static device globals; allocation forbidden)
__device__ __half g_A2[(size_t)AROWS * KSPLIT];  // [images-split ; Y-split]  18.9MB
__device__ __half g_B2[(size_t)CROWS * KSPLIT];  // captions split             8.4MB
__device__ __half g_BW[(size_t)DD   * KSPLIT];   // W_g^T split                4.2MB
__device__ float g_X[(size_t)AROWS * XCOLS];     // fused GEMM output fp32    37.7MB
__device__ float g_G[NB * SS * SS];
__device__ float g_w1[CROWS];

// ---------------------------------------------------------------------------
// PTX helpers (base-ISA only: cp.async, ldmatrix, mma.sync)
// ---------------------------------------------------------------------------
__device__ __forceinline__ uint32_t smem_u32(const void* p) {
    uint32_t a;
    asm("{ .reg .u64 t; cvta.to.shared.u64 t, %1; cvt.u32.u64 %0, t; }" : "=r"(a) : "l"(p));
    return a;
}
#define CP_ASYNC16(dst, src) \
    asm volatile("cp.async.cg.shared.global [%0], [%1], 16;\n" :: "r"(dst), "l"(src))
#define CP_COMMIT() asm volatile("cp.async.commit_group;\n" ::: "memory")
#define CP_WAIT(n)  asm volatile("cp.async.wait_group %0;\n" :: "n"(n) : "memory")

__device__ __forceinline__ void ldsm4(uint32_t* r, uint32_t addr) {
    asm volatile("ldmatrix.sync.aligned.m8n8.x4.shared.b16 {%0,%1,%2,%3}, [%4];"
                 : "=r"(r[0]), "=r"(r[1]), "=r"(r[2]), "=r"(r[3]) : "r"(addr));
}
__device__ __forceinline__ void mma16816(float* c, const uint32_t* a,
                                         uint32_t b0, uint32_t b1) {
    asm volatile("mma.sync.aligned.m16n8k16.row.col.f32.f16.f16.f32 "
                 "{%0,%1,%2,%3}, {%4,%5,%6,%7}, {%8,%9}, {%0,%1,%2,%3};"
                 : "+f"(c[0]), "+f"(c[1]), "+f"(c[2]), "+f"(c[3])
                 : "r"(a[0]), "r"(a[1]), "r"(a[2]), "r"(a[3]), "r"(b0), "r"(b1));
}
// SW128 swizzle for 128B rows
__device__ __forceinline__ uint32_t swz(int row, int seg) {
    return (uint32_t)(row * 128 + (seg ^ ((row & 7) << 4)));
}

// ---------------------------------------------------------------------------
// Split kernels (fp16 two-term)
// A-side pattern: [hi | lo]; B-side pattern: [hi | hi]
// ---------------------------------------------------------------------------
__global__ void split_rows_kernel(const float* __restrict__ src, __half* __restrict__ dst,
                                  int second_is_lo)
{
    int idx = blockIdx.x * 256 + threadIdx.x;
    int row = idx >> 10, col = idx & 1023;
    float f = src[idx];
    __half hi = __float2half(f);
    __half sec = second_is_lo ? __float2half(f - __half2float(hi)) : hi;
    size_t r = (size_t)row * KSPLIT;
    dst[r + col] = hi;
    dst[r + 1024 + col] = sec;
}

// W_g transpose + split (B-side [hi|hi]): g_BW[n][k] = W_g[k][n]
__global__ void split_w_kernel(const float* __restrict__ W)
{
    __shared__ float t[32][33];
    int k0 = blockIdx.y * 32, n0 = blockIdx.x * 32;
    int tx = threadIdx.x, ty = threadIdx.y;
    t[ty][tx] = W[(size_t)(k0 + ty) * DD + n0 + tx];
    __syncthreads();
    float f = t[tx][ty];                       // = W[k0+tx][n0+ty]
    __half hi = __float2half(f);
    size_t r = (size_t)(n0 + ty) * KSPLIT;
    g_BW[r + k0 + tx] = hi;
    g_BW[r + 1024 + k0 + tx] = hi;
}

// ---------------------------------------------------------------------------
// HMMA NT GEMM: C[m,n] = sum_k A[m,k]*B[n,k], K = KSPLIT.
// Templated tile / warp layout; 3-stage cp.async, single barrier per chunk,
// register double-buffered ldmatrix fragments.
// mode 0: write fp32 C (ldc). mode 1: write split fp16 rows [hi|lo] into Aout.
// ---------------------------------------------------------------------------
template<int BM, int BN, int WARPS_M, int WARPS_N, int MIN_CTAS>
__global__ __launch_bounds__(WARPS_M * WARPS_N * 32, MIN_CTAS)
void gemm_mma_kernel(const __half* __restrict__ A,
                     const __half* __restrict__ B,
                     float* __restrict__ C,
                     __half* __restrict__ Aout,
                     int mode, int ldc)
{
    constexpr int THREADS = WARPS_M * WARPS_N * 32;
    constexpr int MT  = BM / WARPS_M / 16;   // A 16-row subtiles per warp
    constexpr int NT2 = BN / WARPS_N / 16;   // B 16-row ldsm tiles per warp
    constexpr int NJ  = NT2 * 2;             // n8 column groups per warp
    constexpr int A_BYTES = BM * 128;
    constexpr int B_BYTES = BN * 128;
    constexpr int STAGE_BYTES = A_BYTES + B_BYTES;
    constexpr int A_IT = BM * 8 / THREADS;
    constexpr int B_IT = BN * 8 / THREADS;

    extern __shared__ char smem_raw[];
    const uint32_t sbase = (smem_u32(smem_raw) + 1023u) & ~1023u;

    const int tid = threadIdx.x;
    const int wid = tid >> 5, lane = tid & 31;
    const int wm = wid / WARPS_N;
    const int wn = wid % WARPS_N;
    const size_t arow0 = (size_t)blockIdx.y * BM;
    const size_t brow0 = (size_t)blockIdx.x * BN;

    const int lr = lane & 15;
    const int lseg = (lane >> 4) * 16;

    float acc[MT][NJ][4];
#pragma unroll
    for (int mt = 0; mt < MT; mt++)
#pragma unroll
        for (int j = 0; j < NJ; j++)
#pragma unroll
            for (int e = 0; e < 4; e++) acc[mt][j][e] = 0.f;

    uint32_t af[2][MT][4], bf[2][NT2][4];

    const char* Abase = (const char*)(A + arow0 * KSPLIT);
    const char* Bbase = (const char*)(B + brow0 * KSPLIT);
    auto load_chunk = [&](int c, int s) {
        const uint32_t sA = sbase + s * STAGE_BYTES;
        const uint32_t sB = sA + A_BYTES;
        const size_t cb = (size_t)c * 128;
#pragma unroll
        for (int i = 0; i < A_IT; i++) {
            int p = tid + i * THREADS;
            int r = p >> 3, seg = (p & 7) * 16;
            CP_ASYNC16(sA + swz(r, seg), Abase + (size_t)r * (KSPLIT * 2) + cb + seg);
        }
#pragma unroll
        for (int i = 0; i < B_IT; i++) {
            int p = tid + i * THREADS;
            int r = p >> 3, seg = (p & 7) * 16;
            CP_ASYNC16(sB + swz(r, seg), Bbase + (size_t)r * (KSPLIT * 2) + cb + seg);
        }
        CP_COMMIT();
    };

    auto ldfrag = [&](int s, int kk, int buf) {
        const uint32_t sA = sbase + s * STAGE_BYTES;
        const uint32_t sB = sA + A_BYTES;
#pragma unroll
        for (int mt = 0; mt < MT; mt++)
            ldsm4(af[buf][mt], sA + swz(wm * (MT * 16) + mt * 16 + lr, kk * 32 + lseg));
#pragma unroll
        for (int nt = 0; nt < NT2; nt++)
            ldsm4(bf[buf][nt], sB + swz(wn * (NT2 * 16) + nt * 16 + lr, kk * 32 + lseg));
    };

    auto domma = [&](int buf) {
#pragma unroll
        for (int mt = 0; mt < MT; mt++)
#pragma unroll
            for (int nt = 0; nt < NT2; nt++)
#pragma unroll
                for (int h = 0; h < 2; h++)
                    mma16816(acc[mt][nt * 2 + h], af[buf][mt],
                             bf[buf][nt][h], bf[buf][nt][h + 2]);
    };

    load_chunk(0, 0);
    load_chunk(1, 1);

    for (int c = 0; c < NCHUNK; c++) {
        // Ensure chunk c complete (committed >=2 iterations ago).
        if (c + 1 < NCHUNK) { CP_WAIT(1); } else { CP_WAIT(0); }
        __syncthreads();   // visibility of chunk c; all warps done with stage (c+2)%3's old tenant
        if (c + 2 < NCHUNK) load_chunk(c + 2, (c + 2) % NSTAGE);
        const int s = c % NSTAGE;
        ldfrag(s, 0, 0);
#pragma unroll
        for (int kk = 0; kk < 4; kk++) {
            if (kk < 3) ldfrag(s, kk + 1, (kk + 1) & 1);
            domma(kk & 1);
        }
    }

    // Epilogue. C-frag mapping: lane l -> rows (l>>2, l>>2+8), cols 2*(l&3)+{0,1}.
    const int r0 = lane >> 2;
    const int cb2 = 2 * (lane & 3);
    if (mode == 0) {
#pragma unroll
        for (int mt = 0; mt < MT; mt++) {
#pragma unroll
            for (int j = 0; j < NJ; j++) {
                size_t row = arow0 + wm * (MT * 16) + mt * 16 + r0;
                size_t col = brow0 + wn * (NJ * 8) + j * 8 + cb2;
                *(float2*)(C + row * ldc + col)       = make_float2(acc[mt][j][0], acc[mt][j][1]);
                *(float2*)(C + (row + 8) * ldc + col) = make_float2(acc[mt][j][2], acc[mt][j][3]);
            }
        }
    } else {
#pragma unroll
        for (int mt = 0; mt < MT; mt++) {
#pragma unroll
            for (int j = 0; j < NJ; j++) {
                int col = (int)brow0 + wn * (NJ * 8) + j * 8 + cb2;   // < 1024
#pragma unroll
                for (int h = 0; h < 2; h++) {
                    size_t row = arow0 + wm * (MT * 16) + mt * 16 + r0 + h * 8;
                    __half* dr = Aout + row * KSPLIT;
                    float f0 = acc[mt][j][2 * h], f1 = acc[mt][j][2 * h + 1];
                    __half h0 = __float2half(f0);
                    __half h1 = __float2half(f1);
                    __half l0 = __float2half(f0 - __half2float(h0));
                    __half l1 = __float2half(f1 - __half2float(h1));
                    __half2 hv; hv.x = h0; hv.y = h1;
                    __half2 lv; lv.x = l0; lv.y = l1;
                    *(__half2*)(dr + col)        = hv;   // [hi | lo]
                    *(__half2*)(dr + 1024 + col) = lv;
                }
            }
        }
    }
}

// ---------------------------------------------------------------------------
// Per-image Gram matrix
// ---------------------------------------------------------------------------
__global__ void gram_kernel(const float* __restrict__ images)
{
    __shared__ float T[SS][65];
    const int b = blockIdx.x;
    const int tid = threadIdx.x;
    float acc[6] = {0.f, 0.f, 0.f, 0.f, 0.f, 0.f};
    for (int d0 = 0; d0 < DD; d0 += 64) {
        __syncthreads();
        for (int i = tid; i < SS * 64; i += 256) {
            int r = i / 64, c = i % 64;
            T[r][c] = images[((size_t)b * SS + r) * DD + d0 + c];
        }
        __syncthreads();
#pragma unroll
        for (int pi = 0; pi < 6; pi++) {
            int p = tid + pi * 256;
            if (p < SS * SS) {
                int s = p / SS, s2 = p % SS;
                float sum = 0.f;
#pragma unroll
                for (int k = 0; k < 64; k++) sum += T[s][k] * T[s2][k];
                acc[pi] += sum;
            }
        }
    }
#pragma unroll
    for (int pi = 0; pi < 6; pi++) {
        int p = tid + pi * 256;
        if (p < SS * SS) g_G[b * SS * SS + p] = acc[pi];
    }
}

__global__ void w1_kernel(const float* __restrict__ captions)
{
    const int row = blockIdx.x * 8 + (threadIdx.x >> 5);
    const int lane = threadIdx.x & 31;
    const float* p = captions + (size_t)row * DD;
    float s = 0.f;
    for (int k = lane; k < DD; k += 32) { float v = p[k]; s += v * v; }
#pragma unroll
    for (int o = 16; o; o >>= 1) s += __shfl_xor_sync(0xffffffffu, s, o);
    if (lane == 0) g_w1[row] = sqrtf(s);
}

// ---------------------------------------------------------------------------
// Final epilogue: one block per (caption i, image b)
// ---------------------------------------------------------------------------
__global__ __launch_bounds__(128)
void epilogue_kernel(const int* __restrict__ cap_lens, float* __restrict__ out)
{
    const int i = blockIdx.x;
    const int b = blockIdx.y;

    __shared__ float sA[SS][LL];
    __shared__ float sC[SS][LL];
    __shared__ float sQ[SS][LL];
    __shared__ float sG[SS][SS];
    __shared__ float snorm[SS];

    const int tid = threadIdx.x;
    const int len = cap_lens[i];

    for (int p = tid; p < SS * SS; p += 128)
        sG[p / SS][p % SS] = g_G[b * SS * SS + p];

    for (int p = tid; p < SS * LL; p += 128) {
        int s = p / LL, l = p % LL;
        size_t col = (size_t)i * LL + l;
        float a = g_X[(size_t)(MROWS + b * SS + s) * XCOLS + col];  // attn logits (Y.cap)
        a = (a > 0.f) ? a : 0.1f * a;
        if (l >= len) a = 0.f;
        sA[s][l] = a;
        sC[s][l] = g_X[(size_t)(b * SS + s) * XCOLS + col];          // cap . img
    }
    __syncthreads();

    if (tid < SS) {
        float s2 = 0.f;
#pragma unroll
        for (int l = 0; l < LL; l++) { float v = sA[tid][l]; s2 += v * v; }
        snorm[tid] = 1.f / (sqrtf(s2) + EPSF);
    }
    __syncthreads();

    if (tid < LL) {
        const int l = tid;
        float vals[SS];
        float m = -CUDART_INF_F;
#pragma unroll
        for (int s = 0; s < SS; s++) {
            float v = sA[s][l] * snorm[s] * SMOOTHF;
            vals[s] = v;
            m = fmaxf(m, v);
        }
        float sum = 0.f;
#pragma unroll
        for (int s = 0; s < SS; s++) {
            float e = expf(vals[s] - m);
            vals[s] = e;
            sum += e;
        }
        float inv = 1.f / sum;
#pragma unroll
        for (int s = 0; s < SS; s++) sA[s][l] = vals[s] * inv;
    }
    __syncthreads();

    for (int p = tid; p < SS * LL; p += 128) {
        int s = p / LL, l = p % LL;
        float sum = 0.f;
#pragma unroll
        for (int s2 = 0; s2 < SS; s2++) sum += sG[s][s2] * sA[s2][l];
        sQ[s][l] = sum;
    }
    __syncthreads();

    if (tid < LL) {
        const int l = tid;
        float w12 = 0.f, w2q = 0.f;
#pragma unroll
        for (int s = 0; s < SS; s++) {
            float p = sA[s][l];
            w12 += p * sC[s][l];
            w2q += p * sQ[s][l];
        }
        float w2 = sqrtf(fmaxf(w2q, 0.f));
        float w1 = g_w1[i * LL + l];
        float r = w12 / fmaxf(w1 * w2, EPSF);

        float z = (l < len) ? r * LAMBDAF : -CUDART_INF_F;
        float m = z;
#pragma unroll
        for (int o = 16; o; o >>= 1) m = fmaxf(m, __shfl_xor_sync(0xffffffffu, m, o));
        float e = (l < len) ? expf(z - m) : 0.f;
#pragma unroll
        for (int o = 16; o; o >>= 1) e += __shfl_xor_sync(0xffffffffu, e, o);
        if (l == 0) out[b * NB + i] = (logf(e) + m) / LAMBDAF;
    }
}

// ---------------------------------------------------------------------------
extern "C" void kernel_launch(void* const* d_in, const int* in_sizes, int n_in,
                              void* d_out, int out_size)
{
    const float* images   = (const float*)d_in[0];  // (64, 36, 1024)
    const float* captions = (const float*)d_in[1];  // (64, 32, 1024)
    const int*   cap_lens = (const int*)  d_in[2];  // (64,)
    const float* W_g      = (const float*)d_in[3];  // (1024, 1024)
    float* out = (float*)d_out;                     // (64, 64)

    __half *pA2, *pB2, *pBW;
    float *pX;
    cudaGetSymbolAddress((void**)&pA2, g_A2);
    cudaGetSymbolAddress((void**)&pB2, g_B2);
    cudaGetSymbolAddress((void**)&pBW, g_BW);
    cudaGetSymbolAddress((void**)&pX,  g_X);

    // P variant: BM=64, BN=64, warps 2x2, 4 CTAs/SM.  smem = 3*(64+64)*128 + 1024 = 50176
    // X variant: BM=128, BN=128, warps 2x4, 2 CTAs/SM. smem = 3*(128+128)*128 + 1024 = 99328
    const int SMEM_P = NSTAGE * (64 + 64) * 128 + 1024;
    const int SMEM_X = NSTAGE * (128 + 128) * 128 + 1024;
    cudaFuncSetAttribute((const void*)gemm_mma_kernel<64, 64, 2, 2, 4>,
                         cudaFuncAttributeMaxDynamicSharedMemorySize, SMEM_P);
    cudaFuncSetAttribute((const void*)gemm_mma_kernel<128, 128, 2, 4, 2>,
                         cudaFuncAttributeMaxDynamicSharedMemorySize, SMEM_X);

    // 1) Splits
    split_rows_kernel<<<MROWS * DD / 256, 256>>>(images, pA2, 1);     // [hi|lo]
    split_rows_kernel<<<CROWS * DD / 256, 256>>>(captions, pB2, 0);   // [hi|hi]
    {
        dim3 grid(DD / 32, DD / 32);
        split_w_kernel<<<grid, dim3(32, 32)>>>(W_g);                  // [hi|hi]
    }

    // 2) GEMM-P: Y = images @ W_g(hi) -> split fp16 [hi|lo] into g_A2 rows [2304, 4608)
    //    grid (16, 36) = 576 CTAs, 128 threads, 4 CTAs/SM
    {
        dim3 grid(DD / 64, MROWS / 64);
        gemm_mma_kernel<64, 64, 2, 2, 4><<<grid, 128, SMEM_P>>>(pA2, pBW, nullptr,
                                                                pA2 + (size_t)MROWS * KSPLIT, 1, 0);
    }
    // 3) GEMM-X: X = [images ; Y] @ captions^T  (4608 x 2048, fp32)
    //    grid (16, 36) = 576 CTAs, 256 threads, 2 CTAs/SM
    {
        dim3 grid(XCOLS / 128, AROWS / 128);
        gemm_mma_kernel<128, 128, 2, 4, 2><<<grid, 256, SMEM_X>>>(pA2, pB2, pX, nullptr, 0, XCOLS);
    }

    // 4) Gram + caption norms
    gram_kernel<<<NB, 256>>>(images);
    w1_kernel<<<CROWS / 8, 256>>>(captions);

    // 5) Final epilogue
    {
        dim3 grid(NB, NB);
        epilogue_kernel<<<grid, 128>>>(cap_lens, out);
    }
}